// round 2
// baseline (speedup 1.0000x reference)
#include <cuda_runtime.h>
#include <cuda_bf16.h>

// Problem: StyleGAN2 modulated+demodulated conv.
// x: (8,128,128,128) NHWC fp32, style: (8,128) fp32, kernel: (3,3,128,128) fp32
// out: (8,128,128,128) NHWC fp32
//
// Plan:
//  K1: per-(b,f) demod scale  s = rsqrt(sum_{p,c} (kernel*(style+1))^2 + 1e-8)
//  K2: Wmod[b][k][f] = kernel[k][f]*(style[b][c]+1)*s[b][f],  k = p*128+c
//  K3: per-batch implicit GEMM: Y[b][m][f] = sum_k A[m][k]*Wmod[b][k][f],
//      A[m][k] = X[b][h+dy][w+dx][c] (zero-padded), M=16384,N=128,K=1152.

#define BATCH 8
#define HW    128
#define CIN   128
#define FOUT  128
#define KK    1152          // 9 * 128
#define BM    128
#define BN    128
#define BK    16
#define NKC   (KK / BK)     // 72 chunks; one chunk = 16 channels of one tap

__device__ float g_wmod[BATCH * KK * FOUT];   // 4.7 MB scratch
__device__ float g_scale[BATCH * FOUT];

// ---------------------------------------------------------------------------
// K1: demod scale per (b, f). 8 blocks x 128 threads.
// ---------------------------------------------------------------------------
__global__ void demod_scale_kernel(const float* __restrict__ style,
                                   const float* __restrict__ kern) {
    int b = blockIdx.x;
    int f = threadIdx.x;
    __shared__ float s_style[CIN];
    s_style[f] = style[b * CIN + f] + 1.0f;
    __syncthreads();

    float sumsq = 0.0f;
    #pragma unroll 4
    for (int k = 0; k < KK; ++k) {
        int c = k & 127;
        float w = kern[k * FOUT + f] * s_style[c];
        sumsq = fmaf(w, w, sumsq);
    }
    g_scale[b * FOUT + f] = rsqrtf(sumsq + 1e-8f);
}

// ---------------------------------------------------------------------------
// K2: write modulated+demodulated weights. grid (1152, 8) x 128 threads.
// ---------------------------------------------------------------------------
__global__ void modw_kernel(const float* __restrict__ style,
                            const float* __restrict__ kern) {
    int k = blockIdx.x;     // 0..1151, k = p*128 + c
    int b = blockIdx.y;
    int f = threadIdx.x;
    int c = k & 127;
    float w = kern[k * FOUT + f] * (style[b * CIN + c] + 1.0f)
            * g_scale[b * FOUT + f];
    g_wmod[((size_t)b * KK + k) * FOUT + f] = w;
}

// ---------------------------------------------------------------------------
// K3: implicit-GEMM conv. grid (128 Mtiles, 8 batches) x 256 threads.
// Each thread computes an 8x8 fp32 tile. Global->reg prefetch of next chunk
// overlaps with the FFMA inner loop.
// ---------------------------------------------------------------------------
__global__ __launch_bounds__(256, 2)
void conv_gemm_kernel(const float* __restrict__ X, float* __restrict__ Y) {
    const int b     = blockIdx.y;
    const int mtile = blockIdx.x;
    const int tid   = threadIdx.x;

    __shared__ float As[BK][BM];        // [k-in-chunk][m]
    __shared__ float Bs[BK][BN];        // [k-in-chunk][f]

    const float* Xb = X + (size_t)b * HW * HW * CIN;
    const float* Wb = g_wmod + (size_t)b * KK * FOUT;

    // ---- A-load mapping: 512 float4 per chunk, 2 per thread ----
    const int ar  = tid >> 2;           // rows ar and ar+64
    const int ac  = (tid & 3) * 4;      // k-in-chunk offset (c offset)
    const int m0  = mtile * BM;
    const int h0  = (m0 + ar) >> 7, w0 = (m0 + ar) & 127;
    const int h1  = (m0 + ar + 64) >> 7, w1 = (m0 + ar + 64) & 127;

    // ---- B-load mapping: 512 float4 per chunk, 2 per thread ----
    const int bk = tid >> 5;            // k rows bk and bk+8
    const int bf = (tid & 31) * 4;

    const int ty = tid >> 4;            // 0..15
    const int tx = tid & 15;            // 0..15

    float acc[8][8];
    #pragma unroll
    for (int i = 0; i < 8; ++i)
        #pragma unroll
        for (int j = 0; j < 8; ++j) acc[i][j] = 0.0f;

    float4 a0, a1, b0v, b1v;

    // prefetch chunk 0
    {
        const int kc = 0;
        const int p = kc >> 3;
        const int cb = ((kc & 7) << 4) + ac;
        const int dy = p / 3 - 1, dx = p % 3 - 1;
        int hh, ww;
        a0 = make_float4(0.f, 0.f, 0.f, 0.f); a1 = a0;
        hh = h0 + dy; ww = w0 + dx;
        if ((unsigned)hh < HW && (unsigned)ww < HW)
            a0 = *(const float4*)(Xb + (((hh << 7) | ww) << 7) + cb);
        hh = h1 + dy; ww = w1 + dx;
        if ((unsigned)hh < HW && (unsigned)ww < HW)
            a1 = *(const float4*)(Xb + (((hh << 7) | ww) << 7) + cb);
        b0v = *(const float4*)(Wb + (kc * BK + bk) * FOUT + bf);
        b1v = *(const float4*)(Wb + (kc * BK + bk + 8) * FOUT + bf);
    }

    for (int kc = 0; kc < NKC; ++kc) {
        // store current chunk to smem
        As[ac + 0][ar]      = a0.x; As[ac + 1][ar]      = a0.y;
        As[ac + 2][ar]      = a0.z; As[ac + 3][ar]      = a0.w;
        As[ac + 0][ar + 64] = a1.x; As[ac + 1][ar + 64] = a1.y;
        As[ac + 2][ar + 64] = a1.z; As[ac + 3][ar + 64] = a1.w;
        *(float4*)&Bs[bk][bf]     = b0v;
        *(float4*)&Bs[bk + 8][bf] = b1v;
        __syncthreads();

        // prefetch next chunk (overlaps with FFMA loop below)
        if (kc + 1 < NKC) {
            const int kn = kc + 1;
            const int p = kn >> 3;
            const int cb = ((kn & 7) << 4) + ac;
            const int dy = p / 3 - 1, dx = p % 3 - 1;
            int hh, ww;
            a0 = make_float4(0.f, 0.f, 0.f, 0.f); a1 = a0;
            hh = h0 + dy; ww = w0 + dx;
            if ((unsigned)hh < HW && (unsigned)ww < HW)
                a0 = *(const float4*)(Xb + (((hh << 7) | ww) << 7) + cb);
            hh = h1 + dy; ww = w1 + dx;
            if ((unsigned)hh < HW && (unsigned)ww < HW)
                a1 = *(const float4*)(Xb + (((hh << 7) | ww) << 7) + cb);
            b0v = *(const float4*)(Wb + (kn * BK + bk) * FOUT + bf);
            b1v = *(const float4*)(Wb + (kn * BK + bk + 8) * FOUT + bf);
        }

        // FFMA inner loop: 16 k-steps x 64 FFMA
        #pragma unroll
        for (int k = 0; k < BK; ++k) {
            float a[8], bb[8];
            *(float4*)&a[0]  = *(const float4*)&As[k][ty * 8];
            *(float4*)&a[4]  = *(const float4*)&As[k][ty * 8 + 4];
            *(float4*)&bb[0] = *(const float4*)&Bs[k][tx * 8];
            *(float4*)&bb[4] = *(const float4*)&Bs[k][tx * 8 + 4];
            #pragma unroll
            for (int i = 0; i < 8; ++i)
                #pragma unroll
                for (int j = 0; j < 8; ++j)
                    acc[i][j] = fmaf(a[i], bb[j], acc[i][j]);
        }
        __syncthreads();
    }

    // epilogue: fp32 float4 stores, fully coalesced
    float* Yb = Y + (size_t)b * HW * HW * FOUT;
    const int mrow = m0 + ty * 8;
    #pragma unroll
    for (int i = 0; i < 8; ++i) {
        float* yr = Yb + (size_t)(mrow + i) * FOUT + tx * 8;
        *(float4*)yr       = make_float4(acc[i][0], acc[i][1], acc[i][2], acc[i][3]);
        *(float4*)(yr + 4) = make_float4(acc[i][4], acc[i][5], acc[i][6], acc[i][7]);
    }
}

// ---------------------------------------------------------------------------
extern "C" void kernel_launch(void* const* d_in, const int* in_sizes, int n_in,
                              void* d_out, int out_size) {
    const float* x     = (const float*)d_in[0];   // (8,128,128,128)
    const float* style = (const float*)d_in[1];   // (8,128)
    const float* kern  = (const float*)d_in[2];   // (3,3,128,128)
    float* y = (float*)d_out;

    demod_scale_kernel<<<BATCH, FOUT>>>(style, kern);
    modw_kernel<<<dim3(KK, BATCH), FOUT>>>(style, kern);
    conv_gemm_kernel<<<dim3(HW * HW / BM, BATCH), 256>>>(x, y);
}

// round 4
// speedup vs baseline: 3.2929x; 3.2929x over previous
#include <cuda_runtime.h>
#include <cuda_bf16.h>
#include <cstdint>

// StyleGAN2 modulated+demodulated conv on GB300.
// x: (8,128,128,128) NHWC fp32, style: (8,128), kernel: (3,3,128,128) -> out NHWC fp32
//
// tcgen05 unavailable (harness compiles at compute_103 base target), so the
// tensor path is classic mma.sync.m16n8k16 bf16 (HMMA) with fp32 accum.
// bf16x3 split: Y ~= Xhi*Whi + Xhi*Wlo + Xlo*Whi  (rel err ~1e-5).
//
// K1 wprep: fused demod scale + modulate, bf16 hi/lo split, layout [b][f][k]
// K2 gemm : per (h,b) CTA: M=128 (w), N=128 (f), K=1152 = 18 chunks of 64.
//           X loaded fp32 and split to bf16 hi/lo inline during STS.

#define HW    128
#define CIN   128
#define FOUT  128
#define BATCH 8
#define KK    1152
#define NCH   18

__device__ __nv_bfloat16 g_whi[BATCH * FOUT * KK];
__device__ __nv_bfloat16 g_wlo[BATCH * FOUT * KK];

// ---------------- asm helpers ----------------
__device__ __forceinline__ uint32_t smem_u32(const void* p) {
    uint32_t a;
    asm("{ .reg .u64 t; cvta.to.shared.u64 t, %1; cvt.u32.u64 %0, t; }"
        : "=r"(a) : "l"(p));
    return a;
}
__device__ __forceinline__ void ldsm4(uint32_t* r, uint32_t addr) {
    asm volatile("ldmatrix.sync.aligned.m8n8.x4.shared.b16 {%0,%1,%2,%3}, [%4];"
                 : "=r"(r[0]), "=r"(r[1]), "=r"(r[2]), "=r"(r[3]) : "r"(addr));
}
__device__ __forceinline__ void mma_bf16(float* c, const uint32_t* a, const uint32_t* b) {
    asm volatile(
        "mma.sync.aligned.m16n8k16.row.col.f32.bf16.bf16.f32 "
        "{%0,%1,%2,%3}, {%4,%5,%6,%7}, {%8,%9}, {%0,%1,%2,%3};"
        : "+f"(c[0]), "+f"(c[1]), "+f"(c[2]), "+f"(c[3])
        : "r"(a[0]), "r"(a[1]), "r"(a[2]), "r"(a[3]), "r"(b[0]), "r"(b[1]));
}
__device__ __forceinline__ void cp_async16(uint32_t saddr, const void* gaddr) {
    asm volatile("cp.async.cg.shared.global [%0], [%1], 16;"
                 :: "r"(saddr), "l"(gaddr));
}
__device__ __forceinline__ void cp_commit() { asm volatile("cp.async.commit_group;"); }
__device__ __forceinline__ void cp_wait0()  { asm volatile("cp.async.wait_group 0;" ::: "memory"); }

__device__ __forceinline__ uint32_t sw128(uint32_t off) {
    return off ^ ((off >> 3) & 0x70);
}

// ---------------------------------------------------------------------------
// K1: fused demod scale + modulate + bf16 hi/lo split, layout [b][f][k].
// grid (128 f, 8 b) x 128 threads (c).
// ---------------------------------------------------------------------------
__global__ void wprep_kernel(const float* __restrict__ style,
                             const float* __restrict__ kern) {
    const int f = blockIdx.x, b = blockIdx.y, c = threadIdx.x;
    const float st = style[b * CIN + c] + 1.0f;
    float wv[9];
    float ss = 0.0f;
    #pragma unroll
    for (int p = 0; p < 9; ++p) {
        float w = kern[(p * 128 + c) * 128 + f] * st;
        wv[p] = w;
        ss = fmaf(w, w, ss);
    }
    __shared__ float red[128];
    red[c] = ss;
    __syncthreads();
    #pragma unroll
    for (int s = 64; s > 0; s >>= 1) {
        if (c < s) red[c] += red[c + s];
        __syncthreads();
    }
    const float scale = rsqrtf(red[0] + 1e-8f);
    const size_t base = (size_t)(b * 128 + f) * KK;
    #pragma unroll
    for (int p = 0; p < 9; ++p) {
        float w = wv[p] * scale;
        __nv_bfloat16 hi = __float2bfloat16(w);
        __nv_bfloat16 lo = __float2bfloat16(w - __bfloat162float(hi));
        g_whi[base + p * 128 + c] = hi;
        g_wlo[base + p * 128 + c] = lo;
    }
}

// ---------------------------------------------------------------------------
// K2: HMMA implicit GEMM. grid (128 h, 8 b) x 256 threads (8 warps).
// Warp layout: 4x2 -> warp tile 32(m) x 64(n).
// Stage layout (64KB): Ahi[128x64] 16K | Alo 16K | Bhi[128x64] 16K | Blo 16K.
// SW128 swizzle on 128B rows for conflict-free ldmatrix/STS.
// ---------------------------------------------------------------------------
#define STAGE_BYTES 65536
#define SMEM_TOTAL  (2 * STAGE_BYTES)

__global__ __launch_bounds__(256, 1)
void mdconv_hmma_kernel(const float* __restrict__ X, float* __restrict__ Y) {
    extern __shared__ __align__(1024) char smem[];
    const uint32_t sb  = smem_u32(smem);
    const int tid  = threadIdx.x;
    const int wid  = tid >> 5;
    const int lane = tid & 31;
    const int h = blockIdx.x;
    const int b = blockIdx.y;

    const int mw = (wid >> 1) * 32;     // warp m offset
    const int nw = (wid & 1) * 64;      // warp n offset

    const float* Xb = X + (size_t)b * HW * HW * CIN;
    const __nv_bfloat16* whi_b = g_whi + (size_t)b * FOUT * KK;
    const __nv_bfloat16* wlo_b = g_wlo + (size_t)b * FOUT * KK;

    // ---- per-thread load mapping: 4 tasks, task t handles (row, 16B seg) ----
    // idx = tid + 256*t : row = idx>>3 (0..127), seg = idx&7
    int trow[4], tseg[4];
    uint32_t tsts[4];                   // swizzled in-stage offset (A-relative)
    #pragma unroll
    for (int t = 0; t < 4; ++t) {
        int idx = tid + 256 * t;
        trow[t] = idx >> 3;
        tseg[t] = idx & 7;
        tsts[t] = sw128((uint32_t)(trow[t] * 128 + tseg[t] * 16));
    }

    // ---- ldmatrix per-lane invariants ----
    // A: row = mbase + (lane&7) + ((lane>>3)&1)*8 ; kb = ks*32 + ((lane>>4)&1)*16
    // B: row = nbase + (lane&7) + ((lane>>4)&1)*8 ; kb = ks*32 + ((lane>>3)&1)*16
    const int arow_l = (lane & 7) + ((lane >> 3) & 1) * 8;
    const int akb_l  = ((lane >> 4) & 1) * 16;
    const int brow_l = (lane & 7) + ((lane >> 4) & 1) * 8;
    const int bkb_l  = ((lane >> 3) & 1) * 16;

    float acc[2][8][4];
    #pragma unroll
    for (int i = 0; i < 2; ++i)
        #pragma unroll
        for (int j = 0; j < 8; ++j)
            #pragma unroll
            for (int q = 0; q < 4; ++q) acc[i][j][q] = 0.0f;

    uint4 av[4][2];                     // prefetched fp32 X (8 floats per task)
    bool  avalid[4];

    // ---- chunk-load helpers (macros to keep everything unrolled) ----
    #define ISSUE_LOADS(kc_, stg_)                                            \
    {                                                                         \
        const int p_  = (kc_) >> 1;                                           \
        const int c0_ = ((kc_) & 1) * 64;                                     \
        const int dy_ = p_ / 3 - 1, dx_ = p_ % 3 - 1;                         \
        const int hh_ = h + dy_;                                              \
        _Pragma("unroll")                                                     \
        for (int t = 0; t < 4; ++t) {                                         \
            const int ws_ = trow[t] + dx_;                                    \
            avalid[t] = ((unsigned)hh_ < HW) && ((unsigned)ws_ < HW);         \
            if (avalid[t]) {                                                  \
                const float* g = Xb + (((size_t)hh_ * HW + ws_) << 7)         \
                               + c0_ + tseg[t] * 8;                           \
                av[t][0] = *(const uint4*)g;                                  \
                av[t][1] = *(const uint4*)(g + 4);                            \
            }                                                                 \
            const size_t bo = (size_t)trow[t] * KK + p_ * 128 + c0_           \
                            + tseg[t] * 8;                                    \
            cp_async16((stg_) + 32768 + tsts[t], whi_b + bo);                 \
            cp_async16((stg_) + 49152 + tsts[t], wlo_b + bo);                 \
        }                                                                     \
        cp_commit();                                                          \
    }

    #define STORE_A(stg_)                                                     \
    {                                                                         \
        _Pragma("unroll")                                                     \
        for (int t = 0; t < 4; ++t) {                                         \
            uint4 hi, lo;                                                     \
            if (avalid[t]) {                                                  \
                float f0 = __uint_as_float(av[t][0].x);                       \
                float f1 = __uint_as_float(av[t][0].y);                       \
                float f2 = __uint_as_float(av[t][0].z);                       \
                float f3 = __uint_as_float(av[t][0].w);                       \
                float f4 = __uint_as_float(av[t][1].x);                       \
                float f5 = __uint_as_float(av[t][1].y);                       \
                float f6 = __uint_as_float(av[t][1].z);                       \
                float f7 = __uint_as_float(av[t][1].w);                       \
                __nv_bfloat162 h01 = __floats2bfloat162_rn(f0, f1);           \
                __nv_bfloat162 h23 = __floats2bfloat162_rn(f2, f3);           \
                __nv_bfloat162 h45 = __floats2bfloat162_rn(f4, f5);           \
                __nv_bfloat162 h67 = __floats2bfloat162_rn(f6, f7);           \
                __nv_bfloat162 l01 = __floats2bfloat162_rn(                   \
                    f0 - __bfloat162float(h01.x), f1 - __bfloat162float(h01.y)); \
                __nv_bfloat162 l23 = __floats2bfloat162_rn(                   \
                    f2 - __bfloat162float(h23.x), f3 - __bfloat162float(h23.y)); \
                __nv_bfloat162 l45 = __floats2bfloat162_rn(                   \
                    f4 - __bfloat162float(h45.x), f5 - __bfloat162float(h45.y)); \
                __nv_bfloat162 l67 = __floats2bfloat162_rn(                   \
                    f6 - __bfloat162float(h67.x), f7 - __bfloat162float(h67.y)); \
                hi = make_uint4(*(uint32_t*)&h01, *(uint32_t*)&h23,           \
                                *(uint32_t*)&h45, *(uint32_t*)&h67);          \
                lo = make_uint4(*(uint32_t*)&l01, *(uint32_t*)&l23,           \
                                *(uint32_t*)&l45, *(uint32_t*)&l67);          \
            } else {                                                          \
                hi = make_uint4(0, 0, 0, 0);                                  \
                lo = hi;                                                      \
            }                                                                 \
            *(uint4*)(smem + ((stg_) - sb) + tsts[t])         = hi;           \
            *(uint4*)(smem + ((stg_) - sb) + 16384 + tsts[t]) = lo;           \
        }                                                                     \
    }

    // ---- prologue: chunk 0 ----
    {
        const uint32_t stg = sb;
        ISSUE_LOADS(0, stg);
        STORE_A(stg);
    }

    for (int kc = 0; kc < NCH; ++kc) {
        const uint32_t stg  = sb + (uint32_t)(kc & 1) * STAGE_BYTES;
        const uint32_t stgn = sb + (uint32_t)((kc + 1) & 1) * STAGE_BYTES;

        cp_wait0();
        __syncthreads();

        if (kc + 1 < NCH) ISSUE_LOADS(kc + 1, stgn);

        // ---- compute on stage stg ----
        const uint32_t aH = stg;
        const uint32_t aL = stg + 16384;
        const uint32_t bH = stg + 32768;
        const uint32_t bL = stg + 49152;

        #pragma unroll
        for (int ks = 0; ks < 4; ++ks) {
            uint32_t Ah[2][4], Al[2][4], Bh[4][4], Bl[4][4];
            #pragma unroll
            for (int mt = 0; mt < 2; ++mt) {
                const int row = mw + mt * 16 + arow_l;
                const uint32_t off = (uint32_t)row * 128
                                   + ((uint32_t)(ks * 32 + akb_l) ^ ((row & 7) * 16));
                ldsm4(Ah[mt], aH + off);
                ldsm4(Al[mt], aL + off);
            }
            #pragma unroll
            for (int np = 0; np < 4; ++np) {
                const int row = nw + np * 16 + brow_l;
                const uint32_t off = (uint32_t)row * 128
                                   + ((uint32_t)(ks * 32 + bkb_l) ^ ((row & 7) * 16));
                ldsm4(Bh[np], bH + off);
                ldsm4(Bl[np], bL + off);
            }
            #pragma unroll
            for (int mt = 0; mt < 2; ++mt)
                #pragma unroll
                for (int np = 0; np < 4; ++np) {
                    mma_bf16(acc[mt][np * 2],     Ah[mt], &Bh[np][0]);
                    mma_bf16(acc[mt][np * 2 + 1], Ah[mt], &Bh[np][2]);
                    mma_bf16(acc[mt][np * 2],     Ah[mt], &Bl[np][0]);
                    mma_bf16(acc[mt][np * 2 + 1], Ah[mt], &Bl[np][2]);
                    mma_bf16(acc[mt][np * 2],     Al[mt], &Bh[np][0]);
                    mma_bf16(acc[mt][np * 2 + 1], Al[mt], &Bh[np][2]);
                }
        }

        if (kc + 1 < NCH) STORE_A(stgn);
    }

    // ---- epilogue: direct STG, c0/c1 rows t/4, c2/c3 rows t/4+8 ----
    float* Yb = Y + (((size_t)b * HW + h) * HW) * FOUT;
    #pragma unroll
    for (int mt = 0; mt < 2; ++mt)
        #pragma unroll
        for (int rg = 0; rg < 2; ++rg) {
            const int m = mw + mt * 16 + rg * 8 + (lane >> 2);
            float* yr = Yb + (size_t)m * FOUT + nw + (lane & 3) * 2;
            #pragma unroll
            for (int nt = 0; nt < 8; ++nt) {
                float2 v;
                v.x = acc[mt][nt][rg * 2];
                v.y = acc[mt][nt][rg * 2 + 1];
                *(float2*)(yr + nt * 8) = v;
            }
        }
    #undef ISSUE_LOADS
    #undef STORE_A
}

// ---------------------------------------------------------------------------
extern "C" void kernel_launch(void* const* d_in, const int* in_sizes, int n_in,
                              void* d_out, int out_size) {
    const float* x     = (const float*)d_in[0];   // (8,128,128,128)
    const float* style = (const float*)d_in[1];   // (8,128)
    const float* kern  = (const float*)d_in[2];   // (3,3,128,128)
    float* y = (float*)d_out;

    cudaFuncSetAttribute(mdconv_hmma_kernel,
                         cudaFuncAttributeMaxDynamicSharedMemorySize, SMEM_TOTAL);

    wprep_kernel<<<dim3(FOUT, BATCH), 128>>>(style, kern);
    mdconv_hmma_kernel<<<dim3(HW, BATCH), 256, SMEM_TOTAL>>>(x, y);
}

// round 5
// speedup vs baseline: 4.2868x; 1.3018x over previous
#include <cuda_runtime.h>
#include <cuda_fp16.h>
#include <cstdint>

// StyleGAN2 modulated+demodulated conv on GB300 (sm_103 base target -> HMMA).
// x: (8,128,128,128) NHWC fp32, style: (8,128), kernel: (3,3,128,128) -> NHWC fp32
//
// fp16 2-product split: X = Xh + Xl exactly (fp16 pair), Wh = fp16(W).
//   Y = Xh*Wh + Xl*Wh = X*Wh ; error = X*(W-Wh) ~ 2^-11 norm-relative.
// K1 wprep: fused demod scale + modulate -> Wh fp16, layout [b][f][k]
// K2 gemm : per (h,b) CTA: M=128 (w), N=128 (f), K=1152 = 18 chunks of 64.
//           X loaded fp32, split to fp16 h/l inline during STS.

#define HW    128
#define CIN   128
#define FOUT  128
#define BATCH 8
#define KK    1152
#define NCH   18

__device__ __half g_wh[BATCH * FOUT * KK];

// ---------------- asm helpers ----------------
__device__ __forceinline__ uint32_t smem_u32(const void* p) {
    uint32_t a;
    asm("{ .reg .u64 t; cvta.to.shared.u64 t, %1; cvt.u32.u64 %0, t; }"
        : "=r"(a) : "l"(p));
    return a;
}
__device__ __forceinline__ void ldsm4(uint32_t* r, uint32_t addr) {
    asm volatile("ldmatrix.sync.aligned.m8n8.x4.shared.b16 {%0,%1,%2,%3}, [%4];"
                 : "=r"(r[0]), "=r"(r[1]), "=r"(r[2]), "=r"(r[3]) : "r"(addr));
}
__device__ __forceinline__ void mma_f16(float* c, const uint32_t* a, const uint32_t* b) {
    asm volatile(
        "mma.sync.aligned.m16n8k16.row.col.f32.f16.f16.f32 "
        "{%0,%1,%2,%3}, {%4,%5,%6,%7}, {%8,%9}, {%0,%1,%2,%3};"
        : "+f"(c[0]), "+f"(c[1]), "+f"(c[2]), "+f"(c[3])
        : "r"(a[0]), "r"(a[1]), "r"(a[2]), "r"(a[3]), "r"(b[0]), "r"(b[1]));
}
__device__ __forceinline__ void cp_async16(uint32_t saddr, const void* gaddr) {
    asm volatile("cp.async.cg.shared.global [%0], [%1], 16;"
                 :: "r"(saddr), "l"(gaddr));
}
__device__ __forceinline__ void cp_commit() { asm volatile("cp.async.commit_group;"); }
__device__ __forceinline__ void cp_wait0()  { asm volatile("cp.async.wait_group 0;" ::: "memory"); }

__device__ __forceinline__ uint32_t sw128(uint32_t off) {
    return off ^ ((off >> 3) & 0x70);
}

// ---------------------------------------------------------------------------
// K1: fused demod scale + modulate -> fp16, layout [b][f][k].
// grid (128 f, 8 b) x 128 threads (c).
// ---------------------------------------------------------------------------
__global__ void wprep_kernel(const float* __restrict__ style,
                             const float* __restrict__ kern) {
    const int f = blockIdx.x, b = blockIdx.y, c = threadIdx.x;
    const float st = style[b * CIN + c] + 1.0f;
    float wv[9];
    float ss = 0.0f;
    #pragma unroll
    for (int p = 0; p < 9; ++p) {
        float w = kern[(p * 128 + c) * 128 + f] * st;
        wv[p] = w;
        ss = fmaf(w, w, ss);
    }
    __shared__ float red[128];
    red[c] = ss;
    __syncthreads();
    #pragma unroll
    for (int s = 64; s > 0; s >>= 1) {
        if (c < s) red[c] += red[c + s];
        __syncthreads();
    }
    const float scale = rsqrtf(red[0] + 1e-8f);
    const size_t base = (size_t)(b * 128 + f) * KK;
    #pragma unroll
    for (int p = 0; p < 9; ++p)
        g_wh[base + p * 128 + c] = __float2half_rn(wv[p] * scale);
}

// ---------------------------------------------------------------------------
// K2: HMMA implicit GEMM. grid (128 h, 8 b) x 256 threads (8 warps).
// Warp layout: 4(m) x 2(n) -> warp tile 32(m) x 64(n).
// Stage (48KB): Ah[128x64] 16K | Al[128x64] 16K | B[128x64] 16K.
// SW128 swizzle on 128B rows; fragments double-buffered across k16 steps.
// ---------------------------------------------------------------------------
#define STAGE_BYTES 49152
#define SMEM_TOTAL  (2 * STAGE_BYTES)

__global__ __launch_bounds__(256, 1)
void mdconv_hmma_kernel(const float* __restrict__ X, float* __restrict__ Y) {
    extern __shared__ __align__(1024) char smem[];
    const uint32_t sb  = smem_u32(smem);
    const int tid  = threadIdx.x;
    const int wid  = tid >> 5;
    const int lane = tid & 31;
    const int h = blockIdx.x;
    const int b = blockIdx.y;

    const int mw = (wid >> 1) * 32;     // warp m offset
    const int nw = (wid & 1) * 64;      // warp n offset

    const float* Xb = X + (size_t)b * HW * HW * CIN;
    const __half* wh_b = g_wh + (size_t)b * FOUT * KK;

    // ---- per-thread load mapping: 4 tasks, task t = (row, 16B seg) ----
    int trow[4], tseg[4];
    uint32_t tsts[4];
    #pragma unroll
    for (int t = 0; t < 4; ++t) {
        int idx = tid + 256 * t;
        trow[t] = idx >> 3;
        tseg[t] = idx & 7;
        tsts[t] = sw128((uint32_t)(trow[t] * 128 + tseg[t] * 16));
    }

    // ---- ldmatrix per-lane invariants ----
    const int arow_l = (lane & 7) + ((lane >> 3) & 1) * 8;
    const int akb_l  = ((lane >> 4) & 1) * 16;
    const int brow_l = (lane & 7) + ((lane >> 4) & 1) * 8;
    const int bkb_l  = ((lane >> 3) & 1) * 16;

    float acc[2][8][4];
    #pragma unroll
    for (int i = 0; i < 2; ++i)
        #pragma unroll
        for (int j = 0; j < 8; ++j)
            #pragma unroll
            for (int q = 0; q < 4; ++q) acc[i][j][q] = 0.0f;

    uint4 av[4][2];
    bool  avalid[4];

    #define ISSUE_LOADS(kc_, stg_)                                            \
    {                                                                         \
        const int p_  = (kc_) >> 1;                                           \
        const int c0_ = ((kc_) & 1) * 64;                                     \
        const int dy_ = p_ / 3 - 1, dx_ = p_ % 3 - 1;                         \
        const int hh_ = h + dy_;                                              \
        _Pragma("unroll")                                                     \
        for (int t = 0; t < 4; ++t) {                                         \
            const int ws_ = trow[t] + dx_;                                    \
            avalid[t] = ((unsigned)hh_ < HW) && ((unsigned)ws_ < HW);         \
            if (avalid[t]) {                                                  \
                const float* g = Xb + (((size_t)hh_ * HW + ws_) << 7)         \
                               + c0_ + tseg[t] * 8;                           \
                av[t][0] = *(const uint4*)g;                                  \
                av[t][1] = *(const uint4*)(g + 4);                            \
            }                                                                 \
            const size_t bo = (size_t)trow[t] * KK + p_ * 128 + c0_           \
                            + tseg[t] * 8;                                    \
            cp_async16((stg_) + 32768 + tsts[t], wh_b + bo);                  \
        }                                                                     \
        cp_commit();                                                          \
    }

    #define STORE_A(stg_)                                                     \
    {                                                                         \
        _Pragma("unroll")                                                     \
        for (int t = 0; t < 4; ++t) {                                         \
            uint4 hi, lo;                                                     \
            if (avalid[t]) {                                                  \
                float f0 = __uint_as_float(av[t][0].x);                       \
                float f1 = __uint_as_float(av[t][0].y);                       \
                float f2 = __uint_as_float(av[t][0].z);                       \
                float f3 = __uint_as_float(av[t][0].w);                       \
                float f4 = __uint_as_float(av[t][1].x);                       \
                float f5 = __uint_as_float(av[t][1].y);                       \
                float f6 = __uint_as_float(av[t][1].z);                       \
                float f7 = __uint_as_float(av[t][1].w);                       \
                __half2 h01 = __floats2half2_rn(f0, f1);                      \
                __half2 h23 = __floats2half2_rn(f2, f3);                      \
                __half2 h45 = __floats2half2_rn(f4, f5);                      \
                __half2 h67 = __floats2half2_rn(f6, f7);                      \
                __half2 l01 = __floats2half2_rn(                              \
                    f0 - __low2float(h01), f1 - __high2float(h01));           \
                __half2 l23 = __floats2half2_rn(                              \
                    f2 - __low2float(h23), f3 - __high2float(h23));           \
                __half2 l45 = __floats2half2_rn(                              \
                    f4 - __low2float(h45), f5 - __high2float(h45));           \
                __half2 l67 = __floats2half2_rn(                              \
                    f6 - __low2float(h67), f7 - __high2float(h67));           \
                hi = make_uint4(*(uint32_t*)&h01, *(uint32_t*)&h23,           \
                                *(uint32_t*)&h45, *(uint32_t*)&h67);          \
                lo = make_uint4(*(uint32_t*)&l01, *(uint32_t*)&l23,           \
                                *(uint32_t*)&l45, *(uint32_t*)&l67);          \
            } else {                                                          \
                hi = make_uint4(0, 0, 0, 0);                                  \
                lo = hi;                                                      \
            }                                                                 \
            *(uint4*)(smem + ((stg_) - sb) + tsts[t])         = hi;           \
            *(uint4*)(smem + ((stg_) - sb) + 16384 + tsts[t]) = lo;           \
        }                                                                     \
    }

    // fragment load for k16-step ks_ into buffer bf_
    #define LOAD_FRAGS(ks_, bf_, aH_, aL_, bB_)                               \
    {                                                                         \
        _Pragma("unroll")                                                     \
        for (int mt = 0; mt < 2; ++mt) {                                      \
            const int row = mw + mt * 16 + arow_l;                            \
            const uint32_t off = (uint32_t)row * 128                          \
                + ((uint32_t)((ks_) * 32 + akb_l) ^ ((row & 7) * 16));        \
            ldsm4(Ah[bf_][mt], (aH_) + off);                                  \
            ldsm4(Al[bf_][mt], (aL_) + off);                                  \
        }                                                                     \
        _Pragma("unroll")                                                     \
        for (int np = 0; np < 4; ++np) {                                      \
            const int row = nw + np * 16 + brow_l;                            \
            const uint32_t off = (uint32_t)row * 128                          \
                + ((uint32_t)((ks_) * 32 + bkb_l) ^ ((row & 7) * 16));        \
            ldsm4(Bh[bf_][np], (bB_) + off);                                  \
        }                                                                     \
    }

    // ---- prologue: chunk 0 ----
    ISSUE_LOADS(0, sb);
    STORE_A(sb);

    uint32_t Ah[2][2][4], Al[2][2][4], Bh[2][4][4];

    for (int kc = 0; kc < NCH; ++kc) {
        const uint32_t stg  = sb + (uint32_t)(kc & 1) * STAGE_BYTES;
        const uint32_t stgn = sb + (uint32_t)((kc + 1) & 1) * STAGE_BYTES;

        cp_wait0();
        __syncthreads();

        if (kc + 1 < NCH) ISSUE_LOADS(kc + 1, stgn);

        const uint32_t aH = stg;
        const uint32_t aL = stg + 16384;
        const uint32_t bB = stg + 32768;

        LOAD_FRAGS(0, 0, aH, aL, bB);
        #pragma unroll
        for (int ks = 0; ks < 4; ++ks) {
            const int cur = ks & 1;
            if (ks < 3) LOAD_FRAGS(ks + 1, cur ^ 1, aH, aL, bB);
            #pragma unroll
            for (int mt = 0; mt < 2; ++mt)
                #pragma unroll
                for (int np = 0; np < 4; ++np) {
                    mma_f16(acc[mt][np * 2],     Ah[cur][mt], &Bh[cur][np][0]);
                    mma_f16(acc[mt][np * 2 + 1], Ah[cur][mt], &Bh[cur][np][2]);
                    mma_f16(acc[mt][np * 2],     Al[cur][mt], &Bh[cur][np][0]);
                    mma_f16(acc[mt][np * 2 + 1], Al[cur][mt], &Bh[cur][np][2]);
                }
        }

        if (kc + 1 < NCH) STORE_A(stgn);
    }

    // ---- epilogue ----
    float* Yb = Y + (((size_t)b * HW + h) * HW) * FOUT;
    #pragma unroll
    for (int mt = 0; mt < 2; ++mt)
        #pragma unroll
        for (int rg = 0; rg < 2; ++rg) {
            const int m = mw + mt * 16 + rg * 8 + (lane >> 2);
            float* yr = Yb + (size_t)m * FOUT + nw + (lane & 3) * 2;
            #pragma unroll
            for (int nt = 0; nt < 8; ++nt) {
                float2 v;
                v.x = acc[mt][nt][rg * 2];
                v.y = acc[mt][nt][rg * 2 + 1];
                *(float2*)(yr + nt * 8) = v;
            }
        }
    #undef ISSUE_LOADS
    #undef STORE_A
    #undef LOAD_FRAGS
}

// ---------------------------------------------------------------------------
extern "C" void kernel_launch(void* const* d_in, const int* in_sizes, int n_in,
                              void* d_out, int out_size) {
    const float* x     = (const float*)d_in[0];   // (8,128,128,128)
    const float* style = (const float*)d_in[1];   // (8,128)
    const float* kern  = (const float*)d_in[2];   // (3,3,128,128)
    float* y = (float*)d_out;

    cudaFuncSetAttribute(mdconv_hmma_kernel,
                         cudaFuncAttributeMaxDynamicSharedMemorySize, SMEM_TOTAL);

    wprep_kernel<<<dim3(FOUT, BATCH), 128>>>(style, kern);
    mdconv_hmma_kernel<<<dim3(HW, BATCH), 256, SMEM_TOTAL>>>(x, y);
}

// round 7
// speedup vs baseline: 8.2624x; 1.9274x over previous
#include <cuda_runtime.h>
#include <cuda_fp16.h>
#include <cstdint>

// StyleGAN2 modulated+demodulated conv on GB300 (sm_103 base target -> HMMA).
// x: (8,128,128,128) NHWC fp32, style: (8,128), kernel: (3,3,128,128) -> NHWC fp32
//
// Single-product fp16 GEMM: Xh = fp16(X), Wh = fp16(W_mod_demod).
//   Y = Xh*Wh ; rounding error ~3e-4 norm-relative (threshold 1e-3).
// K0 split_x: X fp32 -> fp16, same NHWC layout
// K1 wprep  : fused demod scale + modulate -> Wh fp16, layout [b][f][k]
// K2 gemm   : per (h,b) CTA: M=128 (w), N=128 (f), K=1152 = 18 chunks of 64,
//             3-stage cp.async pipeline, 2 CTAs/SM.

#define HW    128
#define CIN   128
#define FOUT  128
#define BATCH 8
#define KK    1152
#define NCH   18

__device__ __half g_xh[BATCH * HW * HW * CIN];
__device__ __half g_wh[BATCH * FOUT * KK];

// ---------------- asm helpers ----------------
__device__ __forceinline__ uint32_t smem_u32(const void* p) {
    uint32_t a;
    asm("{ .reg .u64 t; cvta.to.shared.u64 t, %1; cvt.u32.u64 %0, t; }"
        : "=r"(a) : "l"(p));
    return a;
}
__device__ __forceinline__ void ldsm4(uint32_t* r, uint32_t addr) {
    asm volatile("ldmatrix.sync.aligned.m8n8.x4.shared.b16 {%0,%1,%2,%3}, [%4];"
                 : "=r"(r[0]), "=r"(r[1]), "=r"(r[2]), "=r"(r[3]) : "r"(addr));
}
__device__ __forceinline__ void mma_f16(float* c, const uint32_t* a, const uint32_t* b) {
    asm volatile(
        "mma.sync.aligned.m16n8k16.row.col.f32.f16.f16.f32 "
        "{%0,%1,%2,%3}, {%4,%5,%6,%7}, {%8,%9}, {%0,%1,%2,%3};"
        : "+f"(c[0]), "+f"(c[1]), "+f"(c[2]), "+f"(c[3])
        : "r"(a[0]), "r"(a[1]), "r"(a[2]), "r"(a[3]), "r"(b[0]), "r"(b[1]));
}
// cp.async with zfill: src_size 0 -> write 16 zero bytes
__device__ __forceinline__ void cp_async16z(uint32_t saddr, const void* gaddr,
                                            uint32_t src_size) {
    asm volatile("cp.async.cg.shared.global [%0], [%1], 16, %2;"
                 :: "r"(saddr), "l"(gaddr), "r"(src_size));
}
__device__ __forceinline__ void cp_async16(uint32_t saddr, const void* gaddr) {
    asm volatile("cp.async.cg.shared.global [%0], [%1], 16;"
                 :: "r"(saddr), "l"(gaddr));
}
__device__ __forceinline__ void cp_commit() { asm volatile("cp.async.commit_group;"); }
#define CP_WAIT(n) asm volatile("cp.async.wait_group %0;" :: "n"(n) : "memory")

__device__ __forceinline__ uint32_t sw128(uint32_t off) {
    return off ^ ((off >> 3) & 0x70);
}

// ---------------------------------------------------------------------------
// K0: X fp32 -> fp16. Each thread: 8 floats -> 8 halves (one uint4 store).
// ---------------------------------------------------------------------------
__global__ void split_x_kernel(const float* __restrict__ X) {
    size_t i = ((size_t)blockIdx.x * 256 + threadIdx.x) * 8;
    float4 v0 = *(const float4*)(X + i);
    float4 v1 = *(const float4*)(X + i + 4);
    __half2 h01 = __floats2half2_rn(v0.x, v0.y);
    __half2 h23 = __floats2half2_rn(v0.z, v0.w);
    __half2 h45 = __floats2half2_rn(v1.x, v1.y);
    __half2 h67 = __floats2half2_rn(v1.z, v1.w);
    uint4 o = make_uint4(*(uint32_t*)&h01, *(uint32_t*)&h23,
                         *(uint32_t*)&h45, *(uint32_t*)&h67);
    *(uint4*)(g_xh + i) = o;
}

// ---------------------------------------------------------------------------
// K1: fused demod scale + modulate -> fp16, layout [b][f][k].
// ---------------------------------------------------------------------------
__global__ void wprep_kernel(const float* __restrict__ style,
                             const float* __restrict__ kern) {
    const int f = blockIdx.x, b = blockIdx.y, c = threadIdx.x;
    const float st = style[b * CIN + c] + 1.0f;
    float wv[9];
    float ss = 0.0f;
    #pragma unroll
    for (int p = 0; p < 9; ++p) {
        float w = kern[(p * 128 + c) * 128 + f] * st;
        wv[p] = w;
        ss = fmaf(w, w, ss);
    }
    __shared__ float red[128];
    red[c] = ss;
    __syncthreads();
    #pragma unroll
    for (int s = 64; s > 0; s >>= 1) {
        if (c < s) red[c] += red[c + s];
        __syncthreads();
    }
    const float scale = rsqrtf(red[0] + 1e-8f);
    const size_t base = (size_t)(b * 128 + f) * KK;
    #pragma unroll
    for (int p = 0; p < 9; ++p)
        g_wh[base + p * 128 + c] = __float2half_rn(wv[p] * scale);
}

// ---------------------------------------------------------------------------
// K2: HMMA implicit GEMM. grid (128 h, 8 b) x 256 threads (8 warps), 2 CTA/SM.
// Warp layout: 4(m) x 2(n) -> warp tile 32(m) x 64(n).
// Stage (32KB): A[128x64] 16K | B[128x64] 16K. 3 stages, cp.async pipeline.
// ---------------------------------------------------------------------------
#define STAGE_BYTES 32768
#define NSTAGE 3
#define SMEM_TOTAL  (NSTAGE * STAGE_BYTES)

__global__ __launch_bounds__(256, 2)
void mdconv_hmma_kernel(float* __restrict__ Y) {
    extern __shared__ __align__(1024) char smem[];
    const uint32_t sb  = smem_u32(smem);
    const int tid  = threadIdx.x;
    const int wid  = tid >> 5;
    const int lane = tid & 31;
    const int h = blockIdx.x;
    const int b = blockIdx.y;

    const int mw = (wid >> 1) * 32;     // warp m offset
    const int nw = (wid & 1) * 64;      // warp n offset

    const __half* xh_b = g_xh + (size_t)b * HW * HW * CIN;
    const __half* wh_b = g_wh + (size_t)b * FOUT * KK;

    // ---- per-thread load mapping: 4 tasks each for A and B ----
    int trow[4], tseg[4];
    uint32_t tsts[4];
    #pragma unroll
    for (int t = 0; t < 4; ++t) {
        int idx = tid + 256 * t;
        trow[t] = idx >> 3;             // row 0..127
        tseg[t] = idx & 7;              // 16B unit 0..7
        tsts[t] = sw128((uint32_t)(trow[t] * 128 + tseg[t] * 16));
    }

    // ---- ldmatrix per-lane invariants ----
    const int arow_l = (lane & 7) + ((lane >> 3) & 1) * 8;
    const int akb_l  = ((lane >> 4) & 1) * 16;
    const int brow_l = (lane & 7) + ((lane >> 4) & 1) * 8;
    const int bkb_l  = ((lane >> 3) & 1) * 16;
    const uint32_t aXor = (uint32_t)((arow_l & 7) * 16);
    const uint32_t bXor = (uint32_t)((brow_l & 7) * 16);
    uint32_t aRowOff[2], bRowOff[4];
    #pragma unroll
    for (int mt = 0; mt < 2; ++mt)
        aRowOff[mt] = (uint32_t)(mw + mt * 16 + arow_l) * 128;
    #pragma unroll
    for (int np = 0; np < 4; ++np)
        bRowOff[np] = (uint32_t)(nw + np * 16 + brow_l) * 128 + 16384;

    float acc[2][8][4];
    #pragma unroll
    for (int i = 0; i < 2; ++i)
        #pragma unroll
        for (int j = 0; j < 8; ++j)
            #pragma unroll
            for (int q = 0; q < 4; ++q) acc[i][j][q] = 0.0f;

    // issue all cp.async for chunk kc into stage slot
    #define ISSUE_LOADS(kc_)                                                  \
    {                                                                         \
        const uint32_t stg_ = sb + (uint32_t)((kc_) % NSTAGE) * STAGE_BYTES;  \
        const int p_  = (kc_) >> 1;                                           \
        const int c0_ = ((kc_) & 1) * 64;                                     \
        const int dy_ = p_ / 3 - 1, dx_ = p_ % 3 - 1;                         \
        const int hh_ = h + dy_;                                              \
        const bool hok_ = (unsigned)hh_ < HW;                                 \
        _Pragma("unroll")                                                     \
        for (int t = 0; t < 4; ++t) {                                         \
            const int ws_ = trow[t] + dx_;                                    \
            const bool ok_ = hok_ && ((unsigned)ws_ < HW);                    \
            const __half* ga = ok_                                            \
                ? xh_b + (((size_t)hh_ * HW + ws_) << 7) + c0_ + tseg[t] * 8  \
                : xh_b;                                                       \
            cp_async16z(stg_ + tsts[t], ga, ok_ ? 16u : 0u);                  \
            const size_t bo = (size_t)trow[t] * KK + p_ * 128 + c0_           \
                            + tseg[t] * 8;                                    \
            cp_async16(stg_ + 16384 + tsts[t], wh_b + bo);                    \
        }                                                                     \
        cp_commit();                                                          \
    }

    // ---- prologue: stages 0,1 ----
    ISSUE_LOADS(0);
    ISSUE_LOADS(1);

    for (int kc = 0; kc < NCH; ++kc) {
        if (kc + 1 < NCH) { CP_WAIT(1); } else { CP_WAIT(0); }
        __syncthreads();

        if (kc + 2 < NCH) ISSUE_LOADS(kc + 2);

        const uint32_t stg = sb + (uint32_t)(kc % NSTAGE) * STAGE_BYTES;

        #pragma unroll
        for (int ks = 0; ks < 4; ++ks) {
            uint32_t Af[2][4], Bf[4][4];
            const uint32_t aKs = ((uint32_t)(ks * 32 + akb_l)) ^ aXor;
            const uint32_t bKs = ((uint32_t)(ks * 32 + bkb_l)) ^ bXor;
            #pragma unroll
            for (int mt = 0; mt < 2; ++mt)
                ldsm4(Af[mt], stg + aRowOff[mt] + aKs);
            #pragma unroll
            for (int np = 0; np < 4; ++np)
                ldsm4(Bf[np], stg + bRowOff[np] + bKs);
            #pragma unroll
            for (int mt = 0; mt < 2; ++mt)
                #pragma unroll
                for (int np = 0; np < 4; ++np) {
                    mma_f16(acc[mt][np * 2],     Af[mt], &Bf[np][0]);
                    mma_f16(acc[mt][np * 2 + 1], Af[mt], &Bf[np][2]);
                }
        }
    }

    // ---- epilogue: direct STG ----
    float* Yb = Y + (((size_t)b * HW + h) * HW) * FOUT;
    #pragma unroll
    for (int mt = 0; mt < 2; ++mt)
        #pragma unroll
        for (int rg = 0; rg < 2; ++rg) {
            const int m = mw + mt * 16 + rg * 8 + (lane >> 2);
            float* yr = Yb + (size_t)m * FOUT + nw + (lane & 3) * 2;
            #pragma unroll
            for (int nt = 0; nt < 8; ++nt) {
                float2 v;
                v.x = acc[mt][nt][rg * 2];
                v.y = acc[mt][nt][rg * 2 + 1];
                *(float2*)(yr + nt * 8) = v;
            }
        }
    #undef ISSUE_LOADS
}

// ---------------------------------------------------------------------------
extern "C" void kernel_launch(void* const* d_in, const int* in_sizes, int n_in,
                              void* d_out, int out_size) {
    const float* x     = (const float*)d_in[0];   // (8,128,128,128)
    const float* style = (const float*)d_in[1];   // (8,128)
    const float* kern  = (const float*)d_in[2];   // (3,3,128,128)
    float* y = (float*)d_out;

    cudaFuncSetAttribute(mdconv_hmma_kernel,
                         cudaFuncAttributeMaxDynamicSharedMemorySize, SMEM_TOTAL);

    split_x_kernel<<<(BATCH * HW * HW * CIN) / 8 / 256, 256>>>(x);
    wprep_kernel<<<dim3(FOUT, BATCH), 128>>>(style, kern);
    mdconv_hmma_kernel<<<dim3(HW, BATCH), 256, SMEM_TOTAL>>>(y);
}

// round 8
// speedup vs baseline: 8.7035x; 1.0534x over previous
#include <cuda_runtime.h>
#include <cuda_fp16.h>
#include <cstdint>

// StyleGAN2 modulated+demodulated conv on GB300 (sm_103 base target -> HMMA).
// x: (8,128,128,128) NHWC fp32, style: (8,128), kernel: (3,3,128,128) -> NHWC fp32
//
// Single-product fp16 GEMM: Y = fp16(X) * fp16(W_mod_demod), fp32 accum.
// K0 split_x: X fp32 -> fp16
// K1 wprep  : demod scale + modulate -> fp16 W, layout [b][f][k]
// K2 gemm   : per (h,b) CTA: M=128 (w), N=128 (f), K=1152.
//   A served from 130-row shifted windows: one window per (dy, c-half) stage
//   (6 stages) feeds all 3 dx taps by smem row offset. B: 18 chunks of 64.
//   4 warps, warp tile 64x64, 2 CTAs/SM.

#define HW    128
#define CIN   128
#define FOUT  128
#define BATCH 8
#define KK    1152
#define NCH   18

__device__ __half g_xh[BATCH * HW * HW * CIN];
__device__ __half g_wh[BATCH * FOUT * KK];

// ---------------- asm helpers ----------------
__device__ __forceinline__ uint32_t smem_u32(const void* p) {
    uint32_t a;
    asm("{ .reg .u64 t; cvta.to.shared.u64 t, %1; cvt.u32.u64 %0, t; }"
        : "=r"(a) : "l"(p));
    return a;
}
__device__ __forceinline__ void ldsm4(uint32_t* r, uint32_t addr) {
    asm volatile("ldmatrix.sync.aligned.m8n8.x4.shared.b16 {%0,%1,%2,%3}, [%4];"
                 : "=r"(r[0]), "=r"(r[1]), "=r"(r[2]), "=r"(r[3]) : "r"(addr));
}
__device__ __forceinline__ void mma_f16(float* c, const uint32_t* a, const uint32_t* b) {
    asm volatile(
        "mma.sync.aligned.m16n8k16.row.col.f32.f16.f16.f32 "
        "{%0,%1,%2,%3}, {%4,%5,%6,%7}, {%8,%9}, {%0,%1,%2,%3};"
        : "+f"(c[0]), "+f"(c[1]), "+f"(c[2]), "+f"(c[3])
        : "r"(a[0]), "r"(a[1]), "r"(a[2]), "r"(a[3]), "r"(b[0]), "r"(b[1]));
}
__device__ __forceinline__ void cp_async16z(uint32_t saddr, const void* gaddr,
                                            uint32_t src_size) {
    asm volatile("cp.async.cg.shared.global [%0], [%1], 16, %2;"
                 :: "r"(saddr), "l"(gaddr), "r"(src_size));
}
__device__ __forceinline__ void cp_async16(uint32_t saddr, const void* gaddr) {
    asm volatile("cp.async.cg.shared.global [%0], [%1], 16;"
                 :: "r"(saddr), "l"(gaddr));
}
__device__ __forceinline__ void cp_commit() { asm volatile("cp.async.commit_group;"); }
#define CP_WAIT(n) asm volatile("cp.async.wait_group %0;" :: "n"(n) : "memory")

// ---------------------------------------------------------------------------
// K0: X fp32 -> fp16.
// ---------------------------------------------------------------------------
__global__ void split_x_kernel(const float* __restrict__ X) {
    size_t i = ((size_t)blockIdx.x * 256 + threadIdx.x) * 8;
    float4 v0 = *(const float4*)(X + i);
    float4 v1 = *(const float4*)(X + i + 4);
    __half2 h01 = __floats2half2_rn(v0.x, v0.y);
    __half2 h23 = __floats2half2_rn(v0.z, v0.w);
    __half2 h45 = __floats2half2_rn(v1.x, v1.y);
    __half2 h67 = __floats2half2_rn(v1.z, v1.w);
    uint4 o = make_uint4(*(uint32_t*)&h01, *(uint32_t*)&h23,
                         *(uint32_t*)&h45, *(uint32_t*)&h67);
    *(uint4*)(g_xh + i) = o;
}

// ---------------------------------------------------------------------------
// K1: fused demod scale + modulate -> fp16, layout [b][f][k].
// ---------------------------------------------------------------------------
__global__ void wprep_kernel(const float* __restrict__ style,
                             const float* __restrict__ kern) {
    const int f = blockIdx.x, b = blockIdx.y, c = threadIdx.x;
    const float st = style[b * CIN + c] + 1.0f;
    float wv[9];
    float ss = 0.0f;
    #pragma unroll
    for (int p = 0; p < 9; ++p) {
        float w = kern[(p * 128 + c) * 128 + f] * st;
        wv[p] = w;
        ss = fmaf(w, w, ss);
    }
    __shared__ float red[128];
    red[c] = ss;
    __syncthreads();
    #pragma unroll
    for (int s = 64; s > 0; s >>= 1) {
        if (c < s) red[c] += red[c + s];
        __syncthreads();
    }
    const float scale = rsqrtf(red[0] + 1e-8f);
    const size_t base = (size_t)(b * 128 + f) * KK;
    #pragma unroll
    for (int p = 0; p < 9; ++p)
        g_wh[base + p * 128 + c] = __float2half_rn(wv[p] * scale);
}

// ---------------------------------------------------------------------------
// K2: HMMA implicit GEMM with shifted-window A.
// grid (128 h, 8 b) x 128 threads (4 warps), 2 CTAs/SM.
// Warps 2(m) x 2(n), warp tile 64x64.
// SMEM: A windows 2 x 17408 (130 rows x 128B, SW128), B 3 x 16384.
// ---------------------------------------------------------------------------
#define ABUF_BYTES 17408
#define BBUF_BYTES 16384
#define SMEM_B0    (2 * ABUF_BYTES)               // 34816
#define SMEM_TOTAL (SMEM_B0 + 3 * BBUF_BYTES)     // 83968

__global__ __launch_bounds__(128, 2)
void mdconv_hmma_kernel(float* __restrict__ Y) {
    extern __shared__ __align__(1024) char smem[];
    const uint32_t sb  = smem_u32(smem);
    const int tid  = threadIdx.x;
    const int wid  = tid >> 5;
    const int lane = tid & 31;
    const int h = blockIdx.x;
    const int b = blockIdx.y;

    const int mw = (wid >> 1) * 64;     // warp m offset
    const int nw = (wid & 1) * 64;      // warp n offset

    const __half* xh_b = g_xh + (size_t)b * HW * HW * CIN;
    const __half* wh_b = g_wh + (size_t)b * FOUT * KK;

    // ---- ldmatrix per-lane invariants ----
    const int arow_l = (lane & 7) + ((lane >> 3) & 1) * 8;
    const int akb_l  = ((lane >> 4) & 1) * 16;
    const int brow_l = (lane & 7) + ((lane >> 4) & 1) * 8;
    const int bkb_l  = ((lane >> 3) & 1) * 16;

    int aRowBase[4];
    #pragma unroll
    for (int mt = 0; mt < 4; ++mt) aRowBase[mt] = mw + mt * 16 + arow_l;
    uint32_t bRowOff[4];
    #pragma unroll
    for (int np = 0; np < 4; ++np)
        bRowOff[np] = (uint32_t)(nw + np * 16 + brow_l) * 128;

    float acc[4][8][4];
    #pragma unroll
    for (int i = 0; i < 4; ++i)
        #pragma unroll
        for (int j = 0; j < 8; ++j)
            #pragma unroll
            for (int q = 0; q < 4; ++q) acc[i][j][q] = 0.0f;

    // A window for stage s_: 130 rows (w=-1..128) x 64 ch of X[h+dy][.][c0..c0+63]
    #define ISSUE_A(s_)                                                       \
    {                                                                         \
        const uint32_t abuf = sb + (uint32_t)((s_) & 1) * ABUF_BYTES;         \
        const int dy_ = (s_) / 2 - 1;                                         \
        const int c0_ = ((s_) & 1) * 64;                                      \
        const int hh_ = h + dy_;                                              \
        const bool hok_ = (unsigned)hh_ < HW;                                 \
        _Pragma("unroll")                                                     \
        for (int t = 0; t < 8; ++t) {                                         \
            const int u = tid + 128 * t;                                      \
            const int row = u >> 3, seg = u & 7;                              \
            const int wq = row - 1;                                           \
            const bool ok = hok_ && ((unsigned)wq < HW);                      \
            const __half* ga = ok                                             \
                ? xh_b + (((size_t)hh_ * HW + wq) << 7) + c0_ + seg * 8       \
                : xh_b;                                                       \
            cp_async16z(abuf + row * 128 + ((seg * 16) ^ ((row & 7) * 16)),   \
                        ga, ok ? 16u : 0u);                                   \
        }                                                                     \
        if (tid < 16) {                                                       \
            const int u = 1024 + tid;                                         \
            const int row = u >> 3, seg = u & 7;                              \
            const int wq = row - 1;                                           \
            const bool ok = hok_ && ((unsigned)wq < HW);                      \
            const __half* ga = ok                                             \
                ? xh_b + (((size_t)hh_ * HW + wq) << 7) + c0_ + seg * 8       \
                : xh_b;                                                       \
            cp_async16z(abuf + row * 128 + ((seg * 16) ^ ((row & 7) * 16)),   \
                        ga, ok ? 16u : 0u);                                   \
        }                                                                     \
    }

    #define ISSUE_B(kc_)                                                      \
    {                                                                         \
        const uint32_t bbuf = sb + SMEM_B0                                    \
                            + (uint32_t)((kc_) % 3) * BBUF_BYTES;             \
        const int s_  = (kc_) / 3;                                            \
        const int p_  = (s_ / 2) * 3 + (kc_) % 3;                             \
        const int c0_ = (s_ & 1) * 64;                                        \
        _Pragma("unroll")                                                     \
        for (int t = 0; t < 8; ++t) {                                         \
            const int u = tid + 128 * t;                                      \
            const int f_ = u >> 3, seg = u & 7;                               \
            cp_async16(bbuf + f_ * 128 + ((seg * 16) ^ ((f_ & 7) * 16)),      \
                       wh_b + (size_t)f_ * KK + p_ * 128 + c0_ + seg * 8);    \
        }                                                                     \
    }

    // ---- prologue: groups g0 = {A0,B0}, g1 = {A1,B1} ----
    ISSUE_A(0); ISSUE_B(0); cp_commit();
    ISSUE_A(1); ISSUE_B(1); cp_commit();

    for (int kc = 0; kc < NCH; ++kc) {
        CP_WAIT(1);
        __syncthreads();

        // issue group g_{kc+2}: B chunk kc+2, plus A stage kc/3+1 at dx-group start
        {
            if ((kc % 3) == 0 && (kc / 3 + 1) < 6) ISSUE_A(kc / 3 + 1);
            if (kc + 2 < NCH) ISSUE_B(kc + 2);
            cp_commit();
        }

        const int s    = kc / 3;
        const int dxp1 = kc % 3;               // dx + 1 = row shift into window
        const uint32_t abuf = sb + (uint32_t)(s & 1) * ABUF_BYTES;
        const uint32_t bbuf = sb + SMEM_B0 + (uint32_t)(kc % 3) * BBUF_BYTES;

        #pragma unroll
        for (int ks = 0; ks < 4; ++ks) {
            uint32_t Af[4][4], Bf[4][4];
            #pragma unroll
            for (int mt = 0; mt < 4; ++mt) {
                const int row = aRowBase[mt] + dxp1;
                const uint32_t off = (uint32_t)row * 128
                    + ((uint32_t)(ks * 32 + akb_l) ^ ((row & 7) * 16));
                ldsm4(Af[mt], abuf + off);
            }
            #pragma unroll
            for (int np = 0; np < 4; ++np) {
                const uint32_t off = bRowOff[np]
                    + ((uint32_t)(ks * 32 + bkb_l) ^ (bRowOff[np] & 0x70) * 2);
                ldsm4(Bf[np], bbuf + bRowOff[np]
                      + ((uint32_t)(ks * 32 + bkb_l) ^ (((nw + np * 16 + brow_l) & 7) * 16)));
                (void)off;
            }
            #pragma unroll
            for (int mt = 0; mt < 4; ++mt)
                #pragma unroll
                for (int np = 0; np < 4; ++np) {
                    mma_f16(acc[mt][np * 2],     Af[mt], &Bf[np][0]);
                    mma_f16(acc[mt][np * 2 + 1], Af[mt], &Bf[np][2]);
                }
        }
    }

    // ---- epilogue: direct STG ----
    float* Yb = Y + (((size_t)b * HW + h) * HW) * FOUT;
    #pragma unroll
    for (int mt = 0; mt < 4; ++mt)
        #pragma unroll
        for (int rg = 0; rg < 2; ++rg) {
            const int m = mw + mt * 16 + rg * 8 + (lane >> 2);
            float* yr = Yb + (size_t)m * FOUT + nw + (lane & 3) * 2;
            #pragma unroll
            for (int nt = 0; nt < 8; ++nt) {
                float2 v;
                v.x = acc[mt][nt][rg * 2];
                v.y = acc[mt][nt][rg * 2 + 1];
                *(float2*)(yr + nt * 8) = v;
            }
        }
    #undef ISSUE_A
    #undef ISSUE_B
}

// ---------------------------------------------------------------------------
extern "C" void kernel_launch(void* const* d_in, const int* in_sizes, int n_in,
                              void* d_out, int out_size) {
    const float* x     = (const float*)d_in[0];   // (8,128,128,128)
    const float* style = (const float*)d_in[1];   // (8,128)
    const float* kern  = (const float*)d_in[2];   // (3,3,128,128)
    float* y = (float*)d_out;

    cudaFuncSetAttribute(mdconv_hmma_kernel,
                         cudaFuncAttributeMaxDynamicSharedMemorySize, SMEM_TOTAL);

    split_x_kernel<<<(BATCH * HW * HW * CIN) / 8 / 256, 256>>>(x);
    wprep_kernel<<<dim3(FOUT, BATCH), 128>>>(style, kern);
    mdconv_hmma_kernel<<<dim3(HW, BATCH), 128, SMEM_TOTAL>>>(y);
}